// round 9
// baseline (speedup 1.0000x reference)
#include <cuda_runtime.h>
#include <cuda_fp16.h>
#include <math.h>

// ---------------------------------------------------------------------------
// GatingNeuralAdaptiveBias — fp16 1D e-tables + fp32 2D gate-logit table.
//   e_ch(x)+eb_ch : 1D fp16 tables (128B/entry), lerp in main.
//   ldelta(x0,x1) : 2D fp32 bilinear table (513x1025), built from 1D g-tables.
//   w0 = sigmoid(ldelta * itemp);  out = LN(w0 e0 + w1 e1) . c1 + sbw (folded)
// ---------------------------------------------------------------------------

typedef unsigned int uint;
typedef unsigned short ushort;

#define PI_F 3.14159265358979323846f
#define N0 2048
#define N1 8192
#define NX0 512          // 2D gate grid intervals in x0 (nodes 0..512)
#define NX1 1024         // 2D gate grid intervals in x1 (nodes 0..1024)
#define LD2D_STRIDE 1025

__device__ __align__(256) ushort g_etab0[(N0 + 64) * 64];  // fp16 e+eb
__device__ __align__(256) ushort g_etab1[(N1 + 64) * 64];
__device__ __align__(256) ushort g_gtab0[(N0 + 64) * 64];  // fp16 g (+bgc)
__device__ __align__(256) ushort g_gtab1[(N1 + 64) * 64];
__device__ __align__(16)  float  g_wc[2 * 64 * 64];
__device__ __align__(16)  float  g_ld2d[513 * LD2D_STRIDE + 32];

#define GP_C1  0      // 64 : ln_gamma*Wo
#define GP_WD  64     // 64 : Wg2[:,0]-Wg2[:,1]
#define GP_SC  128    // 4  : itemp, sbw, bg2d, c1s
#define GP_TOT 132
__device__ __align__(16) float g_pre[GP_TOT];

__device__ __forceinline__ float silu_fast(float v) {
    return __fdividef(v, 1.0f + __expf(-v));
}

// ========================= Wc fold kernel ==================================
__global__ void k_wc(const float* __restrict__ W2,
                     const float* __restrict__ fg,
                     const float* __restrict__ Wg1)
{
    const int bid = blockIdx.x;    // 128: ch*64 + j
    const int ch  = bid >> 6;
    const int j   = bid & 63;
    const int o   = threadIdx.x;   // 64
    float acc = 0.0f;
    for (int m = 0; m < 64; m++)
        acc = fmaf(W2[j * 64 + m] * fg[ch * 64 + m], Wg1[(ch * 64 + m) * 64 + o], acc);
    g_wc[ch * 4096 + j * 64 + o] = acc;
}

// ================== 1D table build (16 nodes/block, fused e+g) =============
#define CH0_BLOCKS 129         // ceil(2049/16)
#define CH1_BLOCKS 513         // ceil(8193/16)
__global__ void __launch_bounds__(256)
k_tables(const float* __restrict__ log_scale,
         const float* __restrict__ W1,  const float* __restrict__ b1,
         const float* __restrict__ W2,  const float* __restrict__ b2,
         const float* __restrict__ fg,  const float* __restrict__ fb,
         const float* __restrict__ Wg1, const float* __restrict__ bg1,
         const float* __restrict__ Wg2, const float* __restrict__ bg2,
         const float* __restrict__ temp,
         const float* __restrict__ lng, const float* __restrict__ lnb,
         const float* __restrict__ Wo,  const float* __restrict__ bo)
{
    __shared__ float sW2g[4096];
    __shared__ float sWc[4096];
    __shared__ float sW1[576];
    __shared__ float sb1[64];
    __shared__ float sh[4 * 64];

    const int tid  = threadIdx.x;
    const int ch   = (blockIdx.x < CH0_BLOCKS) ? 0 : 1;
    const int base = ch ? (blockIdx.x - CH0_BLOCKS) * 16 : blockIdx.x * 16;

    if (blockIdx.x == 0) {      // publish main-kernel / 2D-build constants
        if (tid < 64) {
            g_pre[GP_C1 + tid] = lng[tid] * Wo[tid];
            g_pre[GP_WD + tid] = Wg2[tid * 2] - Wg2[tid * 2 + 1];
        }
        if (tid == 128) {
            float s = bo[0], cs = 0.0f;
            for (int k = 0; k < 64; k++) { s += lnb[k] * Wo[k]; cs += lng[k] * Wo[k]; }
            g_pre[GP_SC + 0] = expf(-temp[0]);
            g_pre[GP_SC + 1] = s;
            g_pre[GP_SC + 2] = bg2[0] - bg2[1];
            g_pre[GP_SC + 3] = cs;
        }
    }

    for (int t = tid; t < 4096; t += 256) {
        sW2g[t] = W2[t] * fg[ch * 64 + (t & 63)];
        sWc[t]  = g_wc[ch * 4096 + t];
    }
    for (int t = tid; t < 576; t += 256) sW1[t] = W1[t];
    if (tid < 64) sb1[tid] = b1[tid];

    const int   grp  = tid >> 6;
    const int   dim  = tid & 63;
    const int   ncap = ch ? N1 : N0;
    const float sc   = expf(log_scale[ch]);
    const float eb   = b2[dim] * fg[ch * 64 + dim] + fb[ch * 64 + dim];
    float gb = 0.0f;
    if (ch == 0) {
        gb = bg1[dim];
        for (int k = 0; k < 64; k++) {
            gb = fmaf(b2[k] * fg[k]      + fb[k],      Wg1[k * 64 + dim],        gb);
            gb = fmaf(b2[k] * fg[64 + k] + fb[64 + k], Wg1[(64 + k) * 64 + dim], gb);
        }
    }
    __syncthreads();

    ushort* etab = ch ? g_etab1 : g_etab0;
    ushort* gtab = ch ? g_gtab1 : g_gtab0;

    #pragma unroll 1
    for (int round = 0; round < 4; round++) {
        const int ent = base + round * 4 + grp;
        const float x = ch ? (-PI_F + (float)ent * (2.0f * PI_F / N1))
                           : ((float)ent * (1.0f / N0));
        float ft[9];
        ft[0] = x * sc;
        #pragma unroll
        for (int q = 0; q < 4; q++) {
            float s, c;
            sincosf(x * (float)(1 << q), &s, &c);
            ft[1 + 2 * q] = s * sc;
            ft[2 + 2 * q] = c * sc;
        }
        float z = sb1[dim];
        #pragma unroll
        for (int f = 0; f < 9; f++) z = fmaf(ft[f], sW1[f * 64 + dim], z);
        sh[grp * 64 + dim] = z / (1.0f + expf(-z));
        __syncthreads();

        float e = eb, g = gb;
        #pragma unroll 4
        for (int j = 0; j < 64; j++) {
            const float hj = sh[grp * 64 + j];
            e = fmaf(hj, sW2g[j * 64 + dim], e);
            g = fmaf(hj, sWc[j * 64 + dim],  g);
        }
        if (ent <= ncap) {
            etab[ent * 64 + dim] = __half_as_ushort(__float2half_rn(e));
            gtab[ent * 64 + dim] = __half_as_ushort(__float2half_rn(g));
        }
        __syncthreads();
    }
}

// ================== 2D gate-logit table build ==============================
// grid = 65 chunks (8 x0-nodes each) x 5 segs (256 x1-nodes each)
__global__ void __launch_bounds__(256)
k_gate2d()
{
    __shared__ __half2 s_g0[32];
    __shared__ float   s_wd[64];

    const int tid   = threadIdx.x;
    const int chunk = blockIdx.x / 5;
    const int seg   = blockIdx.x % 5;
    const int i1g   = seg * 256 + tid;
    const bool v1   = (i1g <= NX1);

    if (tid < 64) s_wd[tid] = g_pre[GP_WD + tid];
    const float bg2d = g_pre[GP_SC + 2];

    __half2 r1[32];
    if (v1) {
        const uint4* p = reinterpret_cast<const uint4*>(&g_gtab1[(i1g * 8) * 64]);
        uint4* d = reinterpret_cast<uint4*>(r1);
        #pragma unroll
        for (int c = 0; c < 8; c++) d[c] = __ldg(&p[c]);
    }

    #pragma unroll 1
    for (int r = 0; r < 8; r++) {
        const int i0g = chunk * 8 + r;
        if (i0g > NX0) break;
        if (tid < 32)
            s_g0[tid] = reinterpret_cast<const __half2*>(&g_gtab0[(i0g * 4) * 64])[tid];
        __syncthreads();

        if (v1) {
            float acc = bg2d;
            #pragma unroll 8
            for (int k2 = 0; k2 < 32; k2++) {
                const float2 sm = __half22float2(__hadd2(s_g0[k2], r1[k2]));
                acc = fmaf(silu_fast(sm.x), s_wd[2 * k2],     acc);
                acc = fmaf(silu_fast(sm.y), s_wd[2 * k2 + 1], acc);
            }
            g_ld2d[i0g * LD2D_STRIDE + i1g] = acc;
        }
        __syncthreads();
    }
}

// ========================= main kernel =====================================
__device__ __forceinline__ void lerp8(uint4 A, uint4 B, float f, float* o) {
    const __half2* a = reinterpret_cast<const __half2*>(&A);
    const __half2* b = reinterpret_cast<const __half2*>(&B);
    #pragma unroll
    for (int i = 0; i < 4; i++) {
        const float2 fa = __half22float2(a[i]);
        const float2 fb = __half22float2(b[i]);
        o[2 * i]     = fmaf(f, fb.x - fa.x, fa.x);
        o[2 * i + 1] = fmaf(f, fb.y - fa.y, fa.y);
    }
}

__global__ void __launch_bounds__(256)
gnab_main(const float* __restrict__ coords,
          const float* __restrict__ cost,
          float* __restrict__ out)
{
    __shared__ __align__(16) float s_c1[64];
    __shared__ float s_sc[4];

    const int tid = threadIdx.x;
    if (tid < 64) s_c1[tid] = g_pre[GP_C1 + tid];
    if (tid < 4)  s_sc[tid] = g_pre[GP_SC + tid];
    __syncthreads();

    const int lo = tid & 7;           // lane in oct: dims [lo*8, lo*8+8)
    const int px = tid >> 3;          // 0..31

    const int bid = blockIdx.x;       // 16384 = 2048 rows x 8 segments
    const int row = bid >> 3;
    const int seg = bid & 7;
    const int b = row >> 8;
    const int i = row & 255;
    const int j = seg * 32 + px;
    const int pixel = row * 256 + j;

    const float x0 = __ldg(&cost[pixel]);
    const float dx = __ldg(&coords[(b * 256 + i) * 2 + 0]) - __ldg(&coords[(b * 256 + j) * 2 + 0]);
    const float dy = __ldg(&coords[(b * 256 + i) * 2 + 1]) - __ldg(&coords[(b * 256 + j) * 2 + 1]);
    const float x1 = atan2f(dy, dx);

    // ---- e-table coords ----
    float u0 = x0 * (float)N0;
    int i0 = (int)u0;
    i0 = (i0 < 0) ? 0 : ((i0 > N0 - 1) ? N0 - 1 : i0);
    const float f0 = u0 - (float)i0;

    float u1 = (x1 + PI_F) * ((float)N1 / (2.0f * PI_F));
    int i1 = (int)u1;
    i1 = (i1 < 0) ? 0 : ((i1 > N1 - 1) ? N1 - 1 : i1);
    const float f1 = u1 - (float)i1;

    const uint4* t0 = reinterpret_cast<const uint4*>(g_etab0);
    const uint4* t1 = reinterpret_cast<const uint4*>(g_etab1);
    const uint4 Ea0 = __ldg(&t0[i0 * 8 + lo]);
    const uint4 Eb0 = __ldg(&t0[i0 * 8 + 8 + lo]);
    const uint4 Ea1 = __ldg(&t1[i1 * 8 + lo]);
    const uint4 Eb1 = __ldg(&t1[i1 * 8 + 8 + lo]);

    // ---- gate: 2D bilinear logit ----
    float u0g = x0 * (float)NX0;
    int i0g = (int)u0g;
    i0g = (i0g < 0) ? 0 : ((i0g > NX0 - 1) ? NX0 - 1 : i0g);
    const float f0g = u0g - (float)i0g;
    float u1g = (x1 + PI_F) * ((float)NX1 / (2.0f * PI_F));
    int i1g = (int)u1g;
    i1g = (i1g < 0) ? 0 : ((i1g > NX1 - 1) ? NX1 - 1 : i1g);
    const float f1g = u1g - (float)i1g;

    const float* L = &g_ld2d[i0g * LD2D_STRIDE + i1g];
    const float t00 = __ldg(L), t01 = __ldg(L + 1);
    const float t10 = __ldg(L + LD2D_STRIDE), t11 = __ldg(L + LD2D_STRIDE + 1);
    const float la = fmaf(f1g, t01 - t00, t00);
    const float lb = fmaf(f1g, t11 - t10, t10);
    const float ld = fmaf(f0g, lb - la, la);
    const float w0 = __fdividef(1.0f, 1.0f + __expf(-ld * s_sc[0]));
    const float w1 = 1.0f - w0;

    // ---- e lerps + fused + LN reductions ----
    float le0[8], le1[8];
    lerp8(Ea0, Eb0, f0, le0);
    lerp8(Ea1, Eb1, f1, le1);

    float S = 0.0f, Q = 0.0f, D = 0.0f;
    #pragma unroll
    for (int t = 0; t < 8; t++) {
        const float f = fmaf(w0, le0[t], w1 * le1[t]);
        S += f;
        Q = fmaf(f, f, Q);
        D = fmaf(f, s_c1[lo * 8 + t], D);
    }
    S += __shfl_xor_sync(0xFFFFFFFFu, S, 1);
    S += __shfl_xor_sync(0xFFFFFFFFu, S, 2);
    S += __shfl_xor_sync(0xFFFFFFFFu, S, 4);
    Q += __shfl_xor_sync(0xFFFFFFFFu, Q, 1);
    Q += __shfl_xor_sync(0xFFFFFFFFu, Q, 2);
    Q += __shfl_xor_sync(0xFFFFFFFFu, Q, 4);
    D += __shfl_xor_sync(0xFFFFFFFFu, D, 1);
    D += __shfl_xor_sync(0xFFFFFFFFu, D, 2);
    D += __shfl_xor_sync(0xFFFFFFFFu, D, 4);

    if (lo == 0) {
        const float mu   = S * (1.0f / 64.0f);
        const float var  = Q * (1.0f / 64.0f) - mu * mu;
        const float rstd = rsqrtf(var + 1e-5f);
        const float dot  = D - mu * s_sc[3];
        out[pixel] = fmaf(dot, rstd, s_sc[1]);
    }
}

// ============================ launch =======================================
extern "C" void kernel_launch(void* const* d_in, const int* in_sizes, int n_in,
                              void* d_out, int out_size)
{
    const float* coords = (const float*)d_in[0];
    const float* cost   = (const float*)d_in[1];
    const float* lsc    = (const float*)d_in[2];
    const float* W1     = (const float*)d_in[3];
    const float* b1     = (const float*)d_in[4];
    const float* W2     = (const float*)d_in[5];
    const float* b2     = (const float*)d_in[6];
    const float* fg     = (const float*)d_in[7];
    const float* fb     = (const float*)d_in[8];
    const float* Wg1    = (const float*)d_in[9];
    const float* bg1    = (const float*)d_in[10];
    const float* Wg2    = (const float*)d_in[11];
    const float* bg2    = (const float*)d_in[12];
    const float* temp   = (const float*)d_in[13];
    const float* lng    = (const float*)d_in[14];
    const float* lnb    = (const float*)d_in[15];
    const float* Wo     = (const float*)d_in[16];
    const float* bo     = (const float*)d_in[17];
    float* out          = (float*)d_out;

    k_wc<<<128, 64>>>(W2, fg, Wg1);
    k_tables<<<CH0_BLOCKS + CH1_BLOCKS, 256>>>(
        lsc, W1, b1, W2, b2, fg, fb, Wg1, bg1, Wg2, bg2,
        temp, lng, lnb, Wo, bo);
    k_gate2d<<<65 * 5, 256>>>();
    gnab_main<<<16384, 256>>>(coords, cost, out);
}

// round 10
// speedup vs baseline: 1.6593x; 1.6593x over previous
#include <cuda_runtime.h>
#include <cuda_fp16.h>
#include <math.h>

// ---------------------------------------------------------------------------
// GatingNeuralAdaptiveBias — fp16 1D e-tables + coarse fp32 2D gate table.
//   e_ch(x)+eb_ch : 1D fp16 tables (10242 nodes), lerp in main.
//   ldelta(x0,x1) : 2D fp32 bilinear (129 x 257), from coarse g = h @ Wc.
//   w0 = sigmoid(ldelta*itemp);  out = LN(w0 e0 + w1 e1) . c1 + sbw (folded)
// Setup: K1 consts+Wc fold -> K2 e-tables + coarse g nodes -> K3 2D gate.
// ---------------------------------------------------------------------------

typedef unsigned int uint;
typedef unsigned short ushort;

#define PI_F 3.14159265358979323846f
#define N0   2048
#define N1   8192
#define NXG0 128            // 2D gate intervals in x0 (nodes 0..128)
#define NXG1 256            // 2D gate intervals in x1 (nodes 0..256)
#define LDS2 257

__device__ __align__(256) ushort g_etab0[(N0 + 64) * 64];   // fp16 e+eb
__device__ __align__(256) ushort g_etab1[(N1 + 64) * 64];
__device__ __align__(16)  float  g_wc[2 * 64 * 64];
__device__ __align__(16)  float  g_g0c[(NXG0 + 4) * 64];    // coarse g (ch0, +bgc)
__device__ __align__(16)  float  g_g1c[(NXG1 + 4) * 64];    // coarse g (ch1)
__device__ __align__(16)  float  g_ld2d[129 * LDS2 + 32];

#define GP_C1   0     // 64 : ln_gamma*Wo
#define GP_WD   64    // 64 : Wg2[:,0]-Wg2[:,1]
#define GP_BGC  128   // 64 : folded gate bias
#define GP_SC   192   // 4  : itemp, sbw, bg2d, c1s
#define GP_TOT  196
__device__ __align__(16) float g_pre[GP_TOT];

__device__ __forceinline__ float silu_acc(float v) {   // accurate (table build)
    return v / (1.0f + expf(-v));
}
__device__ __forceinline__ float silu_fast(float v) {
    return __fdividef(v, 1.0f + __expf(-v));
}

// ==================== K1: Wc fold + constants ==============================
__global__ void __launch_bounds__(64)
k_prep(const float* __restrict__ W2,  const float* __restrict__ b2,
       const float* __restrict__ fg,  const float* __restrict__ fb,
       const float* __restrict__ Wg1, const float* __restrict__ bg1,
       const float* __restrict__ Wg2, const float* __restrict__ bg2,
       const float* __restrict__ temp,
       const float* __restrict__ lng, const float* __restrict__ lnb,
       const float* __restrict__ Wo,  const float* __restrict__ bo)
{
    const int blk = blockIdx.x;
    const int tid = threadIdx.x;
    if (blk < 128) {                      // Wc[ch][j][o]
        const int ch = blk >> 6, j = blk & 63;
        float acc = 0.0f;
        #pragma unroll 4
        for (int m = 0; m < 64; m++)
            acc = fmaf(W2[j * 64 + m] * fg[ch * 64 + m],
                       Wg1[(ch * 64 + m) * 64 + tid], acc);
        g_wc[ch * 4096 + j * 64 + tid] = acc;
    } else {                              // constants
        g_pre[GP_C1 + tid] = lng[tid] * Wo[tid];
        g_pre[GP_WD + tid] = Wg2[tid * 2] - Wg2[tid * 2 + 1];
        float gb = bg1[tid];
        #pragma unroll 4
        for (int k = 0; k < 64; k++) {
            gb = fmaf(b2[k] * fg[k]      + fb[k],      Wg1[k * 64 + tid],        gb);
            gb = fmaf(b2[k] * fg[64 + k] + fb[64 + k], Wg1[(64 + k) * 64 + tid], gb);
        }
        g_pre[GP_BGC + tid] = gb;
        if (tid == 0) {
            float s = bo[0], cs = 0.0f;
            for (int k = 0; k < 64; k++) { s += lnb[k] * Wo[k]; cs += lng[k] * Wo[k]; }
            g_pre[GP_SC + 0] = expf(-temp[0]);
            g_pre[GP_SC + 1] = s;
            g_pre[GP_SC + 2] = bg2[0] - bg2[1];
            g_pre[GP_SC + 3] = cs;
        }
    }
}

// ==================== K2: e-tables + coarse g nodes ========================
// block = 64 threads = 4 nodes x 16 threads; thread owns 4 dims (float4).
#define EB0 513     // ceil(2049/4)
#define EB1 2049    // ceil(8193/4)
#define GB0 33      // ceil(129/4)
#define GB1 65      // ceil(257/4)
__global__ void __launch_bounds__(64)
k_tab(const float* __restrict__ log_scale,
      const float* __restrict__ W1, const float* __restrict__ b1,
      const float* __restrict__ W2, const float* __restrict__ b2,
      const float* __restrict__ fg, const float* __restrict__ fb)
{
    __shared__ float sh[4 * 68];

    const int blk = blockIdx.x;
    const int tid = threadIdx.x;
    const int tg  = tid >> 4;          // node within block
    const int tl  = tid & 15;          // dim quad
    const int d0  = tl * 4;

    int mode, ch, base;
    if      (blk < EB0)             { mode = 0; ch = 0; base = blk * 4; }
    else if (blk < EB0 + EB1)       { mode = 0; ch = 1; base = (blk - EB0) * 4; }
    else if (blk < EB0 + EB1 + GB0) { mode = 1; ch = 0; base = (blk - EB0 - EB1) * 4; }
    else                            { mode = 1; ch = 1; base = (blk - EB0 - EB1 - GB0) * 4; }

    const int ent  = base + tg;
    const int ncap = mode ? (ch ? NXG1 : NXG0) : (ch ? N1 : N0);
    const float x  = ch ? (-PI_F + (float)ent * (2.0f * PI_F / (mode ? NXG1 : N1)))
                        : ((float)ent * (mode ? (1.0f / NXG0) : (1.0f / N0)));
    const float sc = expf(log_scale[ch]);

    float ft[9];
    ft[0] = x * sc;
    #pragma unroll
    for (int q = 0; q < 4; q++) {
        float s, c;
        sincosf(x * (float)(1 << q), &s, &c);
        ft[1 + 2 * q] = s * sc;
        ft[2 + 2 * q] = c * sc;
    }

    // h for 4 dims
    float4 z = __ldg(reinterpret_cast<const float4*>(b1 + d0));
    #pragma unroll
    for (int f = 0; f < 9; f++) {
        const float4 w = __ldg(reinterpret_cast<const float4*>(W1 + f * 64 + d0));
        z.x = fmaf(ft[f], w.x, z.x);
        z.y = fmaf(ft[f], w.y, z.y);
        z.z = fmaf(ft[f], w.z, z.z);
        z.w = fmaf(ft[f], w.w, z.w);
    }
    float4 h4;
    h4.x = silu_acc(z.x);  h4.y = silu_acc(z.y);
    h4.z = silu_acc(z.z);  h4.w = silu_acc(z.w);
    *reinterpret_cast<float4*>(&sh[tg * 68 + d0]) = h4;
    __syncthreads();

    const float* wmat = mode ? &g_wc[ch * 4096] : W2;
    float4 acc = make_float4(0.f, 0.f, 0.f, 0.f);
    const float* hrow = &sh[tg * 68];
    #pragma unroll 8
    for (int j = 0; j < 64; j++) {
        const float hj = hrow[j];
        const float4 w = __ldg(reinterpret_cast<const float4*>(wmat + j * 64 + d0));
        acc.x = fmaf(hj, w.x, acc.x);
        acc.y = fmaf(hj, w.y, acc.y);
        acc.z = fmaf(hj, w.z, acc.z);
        acc.w = fmaf(hj, w.w, acc.w);
    }

    if (ent <= ncap) {
        if (mode == 0) {
            const float4 fgv = __ldg(reinterpret_cast<const float4*>(fg + ch * 64 + d0));
            const float4 b2v = __ldg(reinterpret_cast<const float4*>(b2 + d0));
            const float4 fbv = __ldg(reinterpret_cast<const float4*>(fb + ch * 64 + d0));
            const float e0 = fmaf(acc.x, fgv.x, fmaf(b2v.x, fgv.x, fbv.x));
            const float e1 = fmaf(acc.y, fgv.y, fmaf(b2v.y, fgv.y, fbv.y));
            const float e2 = fmaf(acc.z, fgv.z, fmaf(b2v.z, fgv.z, fbv.z));
            const float e3 = fmaf(acc.w, fgv.w, fmaf(b2v.w, fgv.w, fbv.w));
            __half2 p0 = __floats2half2_rn(e0, e1);
            __half2 p1 = __floats2half2_rn(e2, e3);
            ushort* tab = ch ? g_etab1 : g_etab0;
            uint2 pk;
            pk.x = *reinterpret_cast<uint*>(&p0);
            pk.y = *reinterpret_cast<uint*>(&p1);
            *reinterpret_cast<uint2*>(&tab[ent * 64 + d0]) = pk;
        } else {
            if (ch == 0) {
                const float4 gbv = *reinterpret_cast<const float4*>(&g_pre[GP_BGC + d0]);
                acc.x += gbv.x;  acc.y += gbv.y;
                acc.z += gbv.z;  acc.w += gbv.w;
            }
            float* dst = ch ? g_g1c : g_g0c;
            *reinterpret_cast<float4*>(&dst[ent * 64 + d0]) = acc;
        }
    }
}

// ==================== K3: 2D gate-logit table ==============================
__global__ void __launch_bounds__(256)
k_g2d()
{
    __shared__ float s_wd[64];
    const int tid = threadIdx.x;
    if (tid < 64) s_wd[tid] = g_pre[GP_WD + tid];
    __syncthreads();

    const int idx = blockIdx.x * 256 + tid;
    if (idx >= 129 * LDS2) return;
    const int i0 = idx / LDS2;
    const int i1 = idx - i0 * LDS2;

    const float4* a = reinterpret_cast<const float4*>(&g_g0c[i0 * 64]);
    const float4* b = reinterpret_cast<const float4*>(&g_g1c[i1 * 64]);
    float acc = g_pre[GP_SC + 2];
    #pragma unroll 4
    for (int k = 0; k < 16; k++) {
        const float4 av = __ldg(&a[k]);
        const float4 bv = __ldg(&b[k]);
        acc = fmaf(silu_fast(av.x + bv.x), s_wd[4 * k],     acc);
        acc = fmaf(silu_fast(av.y + bv.y), s_wd[4 * k + 1], acc);
        acc = fmaf(silu_fast(av.z + bv.z), s_wd[4 * k + 2], acc);
        acc = fmaf(silu_fast(av.w + bv.w), s_wd[4 * k + 3], acc);
    }
    g_ld2d[idx] = acc;
}

// ========================= main kernel =====================================
__device__ __forceinline__ void lerp8(uint4 A, uint4 B, float f, float* o) {
    const __half2* a = reinterpret_cast<const __half2*>(&A);
    const __half2* b = reinterpret_cast<const __half2*>(&B);
    #pragma unroll
    for (int i = 0; i < 4; i++) {
        const float2 fa = __half22float2(a[i]);
        const float2 fb = __half22float2(b[i]);
        o[2 * i]     = fmaf(f, fb.x - fa.x, fa.x);
        o[2 * i + 1] = fmaf(f, fb.y - fa.y, fa.y);
    }
}

__global__ void __launch_bounds__(256)
gnab_main(const float* __restrict__ coords,
          const float* __restrict__ cost,
          float* __restrict__ out)
{
    __shared__ __align__(16) float s_c1[64];
    __shared__ float s_sc[4];

    const int tid = threadIdx.x;
    if (tid < 64) s_c1[tid] = g_pre[GP_C1 + tid];
    if (tid < 4)  s_sc[tid] = g_pre[GP_SC + tid];
    __syncthreads();

    const int lo = tid & 7;           // lane in oct: dims [lo*8, lo*8+8)
    const int px = tid >> 3;          // 0..31

    const int bid = blockIdx.x;       // 16384 = 2048 rows x 8 segments
    const int row = bid >> 3;
    const int seg = bid & 7;
    const int b = row >> 8;
    const int i = row & 255;
    const int j = seg * 32 + px;
    const int pixel = row * 256 + j;

    const float x0 = __ldg(&cost[pixel]);
    const float dx = __ldg(&coords[(b * 256 + i) * 2 + 0]) - __ldg(&coords[(b * 256 + j) * 2 + 0]);
    const float dy = __ldg(&coords[(b * 256 + i) * 2 + 1]) - __ldg(&coords[(b * 256 + j) * 2 + 1]);
    const float x1 = atan2f(dy, dx);

    // ---- e-table coords ----
    float u0 = x0 * (float)N0;
    int i0 = (int)u0;
    i0 = (i0 < 0) ? 0 : ((i0 > N0 - 1) ? N0 - 1 : i0);
    const float f0 = u0 - (float)i0;

    float u1 = (x1 + PI_F) * ((float)N1 / (2.0f * PI_F));
    int i1 = (int)u1;
    i1 = (i1 < 0) ? 0 : ((i1 > N1 - 1) ? N1 - 1 : i1);
    const float f1 = u1 - (float)i1;

    const uint4* t0 = reinterpret_cast<const uint4*>(g_etab0);
    const uint4* t1 = reinterpret_cast<const uint4*>(g_etab1);
    const uint4 Ea0 = __ldg(&t0[i0 * 8 + lo]);
    const uint4 Eb0 = __ldg(&t0[i0 * 8 + 8 + lo]);
    const uint4 Ea1 = __ldg(&t1[i1 * 8 + lo]);
    const uint4 Eb1 = __ldg(&t1[i1 * 8 + 8 + lo]);

    // ---- gate: 2D bilinear logit ----
    float u0g = x0 * (float)NXG0;
    int i0g = (int)u0g;
    i0g = (i0g < 0) ? 0 : ((i0g > NXG0 - 1) ? NXG0 - 1 : i0g);
    const float f0g = u0g - (float)i0g;
    float u1g = (x1 + PI_F) * ((float)NXG1 / (2.0f * PI_F));
    int i1g = (int)u1g;
    i1g = (i1g < 0) ? 0 : ((i1g > NXG1 - 1) ? NXG1 - 1 : i1g);
    const float f1g = u1g - (float)i1g;

    const float* L = &g_ld2d[i0g * LDS2 + i1g];
    const float t00 = __ldg(L), t01 = __ldg(L + 1);
    const float t10 = __ldg(L + LDS2), t11 = __ldg(L + LDS2 + 1);
    const float la = fmaf(f1g, t01 - t00, t00);
    const float lb = fmaf(f1g, t11 - t10, t10);
    const float ld = fmaf(f0g, lb - la, la);
    const float w0 = __fdividef(1.0f, 1.0f + __expf(-ld * s_sc[0]));
    const float w1 = 1.0f - w0;

    // ---- e lerps + fused + LN reductions ----
    float le0[8], le1[8];
    lerp8(Ea0, Eb0, f0, le0);
    lerp8(Ea1, Eb1, f1, le1);

    float S = 0.0f, Q = 0.0f, D = 0.0f;
    #pragma unroll
    for (int t = 0; t < 8; t++) {
        const float f = fmaf(w0, le0[t], w1 * le1[t]);
        S += f;
        Q = fmaf(f, f, Q);
        D = fmaf(f, s_c1[lo * 8 + t], D);
    }
    S += __shfl_xor_sync(0xFFFFFFFFu, S, 1);
    S += __shfl_xor_sync(0xFFFFFFFFu, S, 2);
    S += __shfl_xor_sync(0xFFFFFFFFu, S, 4);
    Q += __shfl_xor_sync(0xFFFFFFFFu, Q, 1);
    Q += __shfl_xor_sync(0xFFFFFFFFu, Q, 2);
    Q += __shfl_xor_sync(0xFFFFFFFFu, Q, 4);
    D += __shfl_xor_sync(0xFFFFFFFFu, D, 1);
    D += __shfl_xor_sync(0xFFFFFFFFu, D, 2);
    D += __shfl_xor_sync(0xFFFFFFFFu, D, 4);

    if (lo == 0) {
        const float mu   = S * (1.0f / 64.0f);
        const float var  = Q * (1.0f / 64.0f) - mu * mu;
        const float rstd = rsqrtf(var + 1e-5f);
        const float dot  = D - mu * s_sc[3];
        out[pixel] = fmaf(dot, rstd, s_sc[1]);
    }
}

// ============================ launch =======================================
extern "C" void kernel_launch(void* const* d_in, const int* in_sizes, int n_in,
                              void* d_out, int out_size)
{
    const float* coords = (const float*)d_in[0];
    const float* cost   = (const float*)d_in[1];
    const float* lsc    = (const float*)d_in[2];
    const float* W1     = (const float*)d_in[3];
    const float* b1     = (const float*)d_in[4];
    const float* W2     = (const float*)d_in[5];
    const float* b2     = (const float*)d_in[6];
    const float* fg     = (const float*)d_in[7];
    const float* fb     = (const float*)d_in[8];
    const float* Wg1    = (const float*)d_in[9];
    const float* bg1    = (const float*)d_in[10];
    const float* Wg2    = (const float*)d_in[11];
    const float* bg2    = (const float*)d_in[12];
    const float* temp   = (const float*)d_in[13];
    const float* lng    = (const float*)d_in[14];
    const float* lnb    = (const float*)d_in[15];
    const float* Wo     = (const float*)d_in[16];
    const float* bo     = (const float*)d_in[17];
    float* out          = (float*)d_out;

    k_prep<<<129, 64>>>(W2, b2, fg, fb, Wg1, bg1, Wg2, bg2,
                        temp, lng, lnb, Wo, bo);
    k_tab<<<EB0 + EB1 + GB0 + GB1, 64>>>(lsc, W1, b1, W2, b2, fg, fb);
    k_g2d<<<(129 * LDS2 + 255) / 256, 256>>>();
    gnab_main<<<16384, 256>>>(coords, cost, out);
}

// round 11
// speedup vs baseline: 2.0316x; 1.2244x over previous
#include <cuda_runtime.h>
#include <cuda_fp16.h>
#include <math.h>

// ---------------------------------------------------------------------------
// GatingNeuralAdaptiveBias — fp16 1D e-tables (diamond-angle indexed) +
// coarse fp32 2D w0 table. Main kernel: oct-per-pixel, f32x2 packed math.
//   e0(x0), e1(theta(sigma)) : fp16 tables, 2049 nodes each.
//   w0(x0, sigma)            : 129x257 fp32 bilinear (sigmoid pre-applied).
//   out = LN(w0 e0 + w1 e1) . (ln_gamma*Wo) + sbw     (LN folded)
// Setup: K1 = all tables + consts (one kernel), K2 = 2D w0 table.
// ---------------------------------------------------------------------------

typedef unsigned int uint;
typedef unsigned short ushort;
typedef unsigned long long ull;

#define PI_F 3.14159265358979323846f
#define N0   2048
#define N1   2048          // sigma-indexed: sigma in [0,4]
#define NXG0 128
#define NXG1 256
#define LDS2 257

__device__ __align__(256) ushort g_etab0[(N0 + 8) * 64];
__device__ __align__(256) ushort g_etab1[(N1 + 8) * 64];
__device__ __align__(16)  float  g_g0c[(NXG0 + 16) * 64];
__device__ __align__(16)  float  g_g1c[(NXG1 + 16) * 64];
__device__ __align__(16)  float  g_w2d[129 * LDS2 + 32];   // w0 directly

#define GP_C1  0      // 64 : ln_gamma*Wo
#define GP_WD  64     // 64 : Wg2[:,0]-Wg2[:,1]
#define GP_SC  128    // 4  : itemp, sbw, bg2d, c1s
#define GP_TOT 132
__device__ __align__(16) float g_pre[GP_TOT];

__device__ __forceinline__ float silu_acc(float v)  { return v / (1.0f + expf(-v)); }

__device__ __forceinline__ ull pack2(float lo, float hi) {
    ull r;
    asm("mov.b64 %0, {%1, %2};" : "=l"(r) : "f"(lo), "f"(hi));
    return r;
}
__device__ __forceinline__ void unpack2(ull v, float& lo, float& hi) {
    asm("mov.b64 {%0, %1}, %2;" : "=f"(lo), "=f"(hi) : "l"(v));
}
__device__ __forceinline__ ull fma2(ull a, ull b, ull c) {
    ull d;
    asm("fma.rn.f32x2 %0, %1, %2, %3;" : "=l"(d) : "l"(a), "l"(b), "l"(c));
    return d;
}

// theta at a sigma-grid node (build side). sigma in [0,4]; node 0 -> -pi.
__device__ __forceinline__ float theta_from_sigma(float sigma, int ent) {
    if (ent == 0) return -PI_F;
    const float tau = (sigma >= 2.0f) ? sigma - 2.0f : sigma + 2.0f;
    float x, y;
    if      (tau < 1.0f) { x = 1.0f - tau; y = tau; }
    else if (tau < 2.0f) { x = 1.0f - tau; y = 2.0f - tau; }
    else if (tau < 3.0f) { x = tau - 3.0f; y = 2.0f - tau; }
    else                 { x = tau - 3.0f; y = tau - 4.0f; }
    return atan2f(y, x);
}

// ==================== K1: tables + coarse g + consts =======================
#define EBLK  129          // 16 nodes/block, per channel (2064 >= 2049)
#define GBLK0 9            // 144 >= 129
#define GBLK1 17           // 272 >= 257
#define CONST_BLK (EBLK * 2 + GBLK0 + GBLK1)   // 284; grid = 285
__global__ void __launch_bounds__(256)
k_tab(const float* __restrict__ log_scale,
      const float* __restrict__ W1,  const float* __restrict__ b1,
      const float* __restrict__ W2,  const float* __restrict__ b2,
      const float* __restrict__ fg,  const float* __restrict__ fb,
      const float* __restrict__ Wg1, const float* __restrict__ bg1,
      const float* __restrict__ Wg2, const float* __restrict__ bg2,
      const float* __restrict__ temp,
      const float* __restrict__ lng, const float* __restrict__ lnb,
      const float* __restrict__ Wo,  const float* __restrict__ bo)
{
    const int blk = blockIdx.x;
    const int tid = threadIdx.x;

    if (blk == CONST_BLK) {              // constants block
        if (tid < 64) {
            g_pre[GP_C1 + tid] = lng[tid] * Wo[tid];
            g_pre[GP_WD + tid] = Wg2[tid * 2] - Wg2[tid * 2 + 1];
        }
        if (tid == 64) {
            float s = bo[0], cs = 0.0f;
            for (int k = 0; k < 64; k++) { s += lnb[k] * Wo[k]; cs += lng[k] * Wo[k]; }
            g_pre[GP_SC + 0] = expf(-temp[0]);
            g_pre[GP_SC + 1] = s;
            g_pre[GP_SC + 2] = bg2[0] - bg2[1];
            g_pre[GP_SC + 3] = cs;
        }
        return;
    }

    __shared__ float sh[16 * 68];
    __shared__ float se[16 * 68];

    int mode, ch, base;
    if      (blk < EBLK)              { mode = 0; ch = 0; base = blk * 16; }
    else if (blk < 2 * EBLK)          { mode = 0; ch = 1; base = (blk - EBLK) * 16; }
    else if (blk < 2 * EBLK + GBLK0)  { mode = 1; ch = 0; base = (blk - 2 * EBLK) * 16; }
    else                              { mode = 1; ch = 1; base = (blk - 2 * EBLK - GBLK0) * 16; }

    const int ng  = tid >> 4;           // node in block (0..15)
    const int d0  = (tid & 15) * 4;     // dim quad
    const int ent = base + ng;
    const int ncap = mode ? (ch ? NXG1 : NXG0) : (ch ? N1 : N0);

    float x;
    if (ch == 0) {
        x = (float)ent * (mode ? (1.0f / NXG0) : (1.0f / N0));
    } else {
        const float sig = (float)ent * (mode ? (4.0f / NXG1) : (4.0f / N1));
        x = theta_from_sigma(sig, ent);
    }
    const float sc = expf(log_scale[ch]);

    float ft[9];
    ft[0] = x * sc;
    #pragma unroll
    for (int q = 0; q < 4; q++) {
        float s, c;
        sincosf(x * (float)(1 << q), &s, &c);
        ft[1 + 2 * q] = s * sc;
        ft[2 + 2 * q] = c * sc;
    }

    // h quad
    float4 z = __ldg(reinterpret_cast<const float4*>(b1 + d0));
    #pragma unroll
    for (int f = 0; f < 9; f++) {
        const float4 w = __ldg(reinterpret_cast<const float4*>(W1 + f * 64 + d0));
        z.x = fmaf(ft[f], w.x, z.x);
        z.y = fmaf(ft[f], w.y, z.y);
        z.z = fmaf(ft[f], w.z, z.z);
        z.w = fmaf(ft[f], w.w, z.w);
    }
    float4 h4;
    h4.x = silu_acc(z.x);  h4.y = silu_acc(z.y);
    h4.z = silu_acc(z.z);  h4.w = silu_acc(z.w);
    *reinterpret_cast<float4*>(&sh[ng * 68 + d0]) = h4;
    __syncthreads();

    // e_full quad = (h @ W2 + b2)*gamma + beta
    float4 acc = make_float4(0.f, 0.f, 0.f, 0.f);
    const float* hrow = &sh[ng * 68];
    #pragma unroll 8
    for (int j = 0; j < 64; j++) {
        const float hj = hrow[j];
        const float4 w = __ldg(reinterpret_cast<const float4*>(W2 + j * 64 + d0));
        acc.x = fmaf(hj, w.x, acc.x);
        acc.y = fmaf(hj, w.y, acc.y);
        acc.z = fmaf(hj, w.z, acc.z);
        acc.w = fmaf(hj, w.w, acc.w);
    }
    const float4 fgv = __ldg(reinterpret_cast<const float4*>(fg + ch * 64 + d0));
    const float4 b2v = __ldg(reinterpret_cast<const float4*>(b2 + d0));
    const float4 fbv = __ldg(reinterpret_cast<const float4*>(fb + ch * 64 + d0));
    float4 e4;
    e4.x = fmaf(acc.x + b2v.x, fgv.x, fbv.x);
    e4.y = fmaf(acc.y + b2v.y, fgv.y, fbv.y);
    e4.z = fmaf(acc.z + b2v.z, fgv.z, fbv.z);
    e4.w = fmaf(acc.w + b2v.w, fgv.w, fbv.w);

    if (mode == 0) {
        if (ent <= ncap) {
            __half2 p0 = __floats2half2_rn(e4.x, e4.y);
            __half2 p1 = __floats2half2_rn(e4.z, e4.w);
            ushort* tab = ch ? g_etab1 : g_etab0;
            uint2 pk;
            pk.x = *reinterpret_cast<uint*>(&p0);
            pk.y = *reinterpret_cast<uint*>(&p1);
            *reinterpret_cast<uint2*>(&tab[ent * 64 + d0]) = pk;
        }
    } else {
        // second stage: g = e_full @ Wg1_half (+ bg1 for ch0)
        *reinterpret_cast<float4*>(&se[ng * 68 + d0]) = e4;
        __syncthreads();
        float4 g4 = make_float4(0.f, 0.f, 0.f, 0.f);
        const float* erow = &se[ng * 68];
        #pragma unroll 8
        for (int k = 0; k < 64; k++) {
            const float ek = erow[k];
            const float4 w = __ldg(reinterpret_cast<const float4*>(Wg1 + (ch * 64 + k) * 64 + d0));
            g4.x = fmaf(ek, w.x, g4.x);
            g4.y = fmaf(ek, w.y, g4.y);
            g4.z = fmaf(ek, w.z, g4.z);
            g4.w = fmaf(ek, w.w, g4.w);
        }
        if (ch == 0) {
            const float4 bg = __ldg(reinterpret_cast<const float4*>(bg1 + d0));
            g4.x += bg.x;  g4.y += bg.y;  g4.z += bg.z;  g4.w += bg.w;
        }
        if (ent <= ncap) {
            float* dst = ch ? g_g1c : g_g0c;
            *reinterpret_cast<float4*>(&dst[ent * 64 + d0]) = g4;
        }
    }
}

// ==================== K2: 2D w0 table ======================================
__global__ void __launch_bounds__(256)
k_g2d()
{
    __shared__ float s_wd[64];
    const int tid = threadIdx.x;
    if (tid < 64) s_wd[tid] = g_pre[GP_WD + tid];
    __syncthreads();

    const int idx = blockIdx.x * 256 + tid;
    if (idx >= 129 * LDS2) return;
    const int i0 = idx / LDS2;
    const int i1 = idx - i0 * LDS2;

    const float4* a = reinterpret_cast<const float4*>(&g_g0c[i0 * 64]);
    const float4* b = reinterpret_cast<const float4*>(&g_g1c[i1 * 64]);
    float acc = g_pre[GP_SC + 2];
    #pragma unroll 4
    for (int k = 0; k < 16; k++) {
        const float4 av = __ldg(&a[k]);
        const float4 bv = __ldg(&b[k]);
        acc = fmaf(silu_acc(av.x + bv.x), s_wd[4 * k],     acc);
        acc = fmaf(silu_acc(av.y + bv.y), s_wd[4 * k + 1], acc);
        acc = fmaf(silu_acc(av.z + bv.z), s_wd[4 * k + 2], acc);
        acc = fmaf(silu_acc(av.w + bv.w), s_wd[4 * k + 3], acc);
    }
    g_w2d[idx] = 1.0f / (1.0f + expf(-acc * g_pre[GP_SC + 0]));
}

// ========================= main kernel =====================================
// packed lerp: o[i] = f2*fb + (1-f2)*fa  over 8 dims (fma-only f32x2)
__device__ __forceinline__ void lerp8p(uint4 A, uint4 B, ull f2, ull omf2,
                                       ull zero2, ull* o) {
    const __half2* a = reinterpret_cast<const __half2*>(&A);
    const __half2* b = reinterpret_cast<const __half2*>(&B);
    #pragma unroll
    for (int i = 0; i < 4; i++) {
        const float2 fa = __half22float2(a[i]);
        const float2 fb = __half22float2(b[i]);
        o[i] = fma2(f2, pack2(fb.x, fb.y),
                    fma2(omf2, pack2(fa.x, fa.y), zero2));
    }
}

__global__ void __launch_bounds__(256)
gnab_main(const float* __restrict__ coords,
          const float* __restrict__ cost,
          float* __restrict__ out)
{
    __shared__ __align__(16) float s_c1[64];
    __shared__ float s_sc[4];

    const int tid = threadIdx.x;
    if (tid < 64) s_c1[tid] = g_pre[GP_C1 + tid];
    if (tid < 4)  s_sc[tid] = g_pre[GP_SC + tid];
    __syncthreads();

    const int lo = tid & 7;
    const int px = tid >> 3;

    const int bid = blockIdx.x;       // 16384 = 2048 rows x 8 segments
    const int row = bid >> 3;
    const int seg = bid & 7;
    const int b = row >> 8;
    const int i = row & 255;
    const int j = seg * 32 + px;
    const int pixel = row * 256 + j;

    const float x0 = __ldg(&cost[pixel]);
    const float dx = __ldg(&coords[(b * 256 + i) * 2 + 0]) - __ldg(&coords[(b * 256 + j) * 2 + 0]);
    const float dy = __ldg(&coords[(b * 256 + i) * 2 + 1]) - __ldg(&coords[(b * 256 + j) * 2 + 1]);

    // diamond pseudo-angle sigma in [0,4] (node 0 <-> -pi, node N <-> +pi)
    const float ax = fabsf(dx), ay = fabsf(dy);
    const float den = ax + ay;
    const float t = (den > 0.0f) ? __fdividef(ay, den) : 0.0f;
    float tau;
    if (dx >= 0.0f) tau = (dy >= 0.0f) ? t : 4.0f - t;
    else            tau = (dy >= 0.0f) ? 2.0f - t : 2.0f + t;
    const float sigma = (tau > 2.0f) ? tau - 2.0f : tau + 2.0f;

    // e-table coords
    float u0 = x0 * (float)N0;
    int i0 = (int)u0;
    i0 = (i0 < 0) ? 0 : ((i0 > N0 - 1) ? N0 - 1 : i0);
    const float f0 = u0 - (float)i0;

    float u1 = sigma * ((float)N1 * 0.25f);
    int i1 = (int)u1;
    i1 = (i1 < 0) ? 0 : ((i1 > N1 - 1) ? N1 - 1 : i1);
    const float f1 = u1 - (float)i1;

    const uint4* t0 = reinterpret_cast<const uint4*>(g_etab0);
    const uint4* t1 = reinterpret_cast<const uint4*>(g_etab1);
    const uint4 Ea0 = __ldg(&t0[i0 * 8 + lo]);
    const uint4 Eb0 = __ldg(&t0[i0 * 8 + 8 + lo]);
    const uint4 Ea1 = __ldg(&t1[i1 * 8 + lo]);
    const uint4 Eb1 = __ldg(&t1[i1 * 8 + 8 + lo]);

    // gate: bilinear w0 from 2D table
    float u0g = x0 * (float)NXG0;
    int i0g = (int)u0g;
    i0g = (i0g < 0) ? 0 : ((i0g > NXG0 - 1) ? NXG0 - 1 : i0g);
    const float f0g = u0g - (float)i0g;
    float u1g = sigma * ((float)NXG1 * 0.25f);
    int i1g = (int)u1g;
    i1g = (i1g < 0) ? 0 : ((i1g > NXG1 - 1) ? NXG1 - 1 : i1g);
    const float f1g = u1g - (float)i1g;

    const float* L = &g_w2d[i0g * LDS2 + i1g];
    const float t00 = __ldg(L), t01 = __ldg(L + 1);
    const float t10 = __ldg(L + LDS2), t11 = __ldg(L + LDS2 + 1);
    const float la = fmaf(f1g, t01 - t00, t00);
    const float lb = fmaf(f1g, t11 - t10, t10);
    const float w0 = fmaf(f0g, lb - la, la);
    const float w1 = 1.0f - w0;

    // packed lerps + fused + LN reductions (fma.rn.f32x2 only)
    const ull zero2 = pack2(0.0f, 0.0f);
    ull e0p[4], e1p[4];
    lerp8p(Ea0, Eb0, pack2(f0, f0), pack2(1.0f - f0, 1.0f - f0), zero2, e0p);
    lerp8p(Ea1, Eb1, pack2(f1, f1), pack2(1.0f - f1, 1.0f - f1), zero2, e1p);

    const ull w0_2 = pack2(w0, w0);
    const ull w1_2 = pack2(w1, w1);
    const ull one2 = pack2(1.0f, 1.0f);
    ull S2 = zero2, Q2 = zero2, D2 = zero2;
    const ull* c1u = reinterpret_cast<const ull*>(s_c1) + lo * 4;
    #pragma unroll
    for (int q = 0; q < 4; q++) {
        const ull fv = fma2(w0_2, e0p[q], fma2(w1_2, e1p[q], zero2));
        S2 = fma2(one2, fv, S2);
        Q2 = fma2(fv, fv, Q2);
        D2 = fma2(fv, c1u[q], D2);
    }
    float sa, sb, qa, qb, da, db;
    unpack2(S2, sa, sb);
    unpack2(Q2, qa, qb);
    unpack2(D2, da, db);
    float S = sa + sb, Q = qa + qb, D = da + db;

    S += __shfl_xor_sync(0xFFFFFFFFu, S, 1);
    S += __shfl_xor_sync(0xFFFFFFFFu, S, 2);
    S += __shfl_xor_sync(0xFFFFFFFFu, S, 4);
    Q += __shfl_xor_sync(0xFFFFFFFFu, Q, 1);
    Q += __shfl_xor_sync(0xFFFFFFFFu, Q, 2);
    Q += __shfl_xor_sync(0xFFFFFFFFu, Q, 4);
    D += __shfl_xor_sync(0xFFFFFFFFu, D, 1);
    D += __shfl_xor_sync(0xFFFFFFFFu, D, 2);
    D += __shfl_xor_sync(0xFFFFFFFFu, D, 4);

    if (lo == 0) {
        const float mu   = S * (1.0f / 64.0f);
        const float var  = Q * (1.0f / 64.0f) - mu * mu;
        const float rstd = rsqrtf(var + 1e-5f);
        const float dot  = D - mu * s_sc[3];
        out[pixel] = fmaf(dot, rstd, s_sc[1]);
    }
}

// ============================ launch =======================================
extern "C" void kernel_launch(void* const* d_in, const int* in_sizes, int n_in,
                              void* d_out, int out_size)
{
    const float* coords = (const float*)d_in[0];
    const float* cost   = (const float*)d_in[1];
    const float* lsc    = (const float*)d_in[2];
    const float* W1     = (const float*)d_in[3];
    const float* b1     = (const float*)d_in[4];
    const float* W2     = (const float*)d_in[5];
    const float* b2     = (const float*)d_in[6];
    const float* fg     = (const float*)d_in[7];
    const float* fb     = (const float*)d_in[8];
    const float* Wg1    = (const float*)d_in[9];
    const float* bg1    = (const float*)d_in[10];
    const float* Wg2    = (const float*)d_in[11];
    const float* bg2    = (const float*)d_in[12];
    const float* temp   = (const float*)d_in[13];
    const float* lng    = (const float*)d_in[14];
    const float* lnb    = (const float*)d_in[15];
    const float* Wo     = (const float*)d_in[16];
    const float* bo     = (const float*)d_in[17];
    float* out          = (float*)d_out;

    k_tab<<<CONST_BLK + 1, 256>>>(lsc, W1, b1, W2, b2, fg, fb,
                                  Wg1, bg1, Wg2, bg2, temp, lng, lnb, Wo, bo);
    k_g2d<<<(129 * LDS2 + 255) / 256, 256>>>();
    gnab_main<<<16384, 256>>>(coords, cost, out);
}